// round 1
// baseline (speedup 1.0000x reference)
#include <cuda_runtime.h>
#include <cuda_bf16.h>
#include <math.h>

#define NN 40000
#define EE 600000
#define HC 128          // H*C
#define FUSED 384

// ---------------- scratch (device globals; no allocation allowed) -------------
__device__ float g_xw[3][NN * HC];      // per-category transformed features
__device__ float g_as[3][NN * 2];       // a_src per node/head
__device__ float g_ad[3][NN * 2];       // a_dst per node/head
__device__ float g_s [3][NN * 2];       // softmax denominators
__device__ float g_hcat[NN * FUSED];    // concatenated accumulator / ELU output

// ---------------- kernel A: xw = x @ W  (register-tiled skinny GEMM) ----------
template <int DIN, int RT>
__global__ void gemm_xw_kernel(const float* __restrict__ x,
                               const float* __restrict__ W,
                               float* __restrict__ xw)
{
    __shared__ float xs[RT * DIN];
    const int c = threadIdx.x;              // 0..127 output column
    const int ngroups = NN / RT;
    for (int g = blockIdx.x; g < ngroups; g += gridDim.x) {
        const int n0 = g * RT;
        __syncthreads();
        for (int i = threadIdx.x; i < RT * DIN; i += 128)
            xs[i] = x[n0 * DIN + i];
        __syncthreads();
        float acc[RT];
#pragma unroll
        for (int r = 0; r < RT; r++) acc[r] = 0.f;
#pragma unroll 4
        for (int k = 0; k < DIN; k++) {
            const float w = W[k * HC + c];
#pragma unroll
            for (int r = 0; r < RT; r++) acc[r] += xs[r * DIN + k] * w;
        }
#pragma unroll
        for (int r = 0; r < RT; r++) xw[(n0 + r) * HC + c] = acc[r];
    }
}

// ---------------- kernel A2: per-node attention dots --------------------------
__global__ void att_dots_kernel(const float* __restrict__ xw,
                                const float* __restrict__ att_s,
                                const float* __restrict__ att_d,
                                float* __restrict__ as_,
                                float* __restrict__ ad_)
{
    __shared__ float red[4][2];
    const int c = threadIdx.x;          // 0..127, head = c/64
    const float vs = att_s[c];
    const float vd = att_d[c];
    for (int n = blockIdx.x; n < NN; n += gridDim.x) {
        const float v = xw[n * HC + c];
        float ps = v * vs, pd = v * vd;
#pragma unroll
        for (int o = 16; o; o >>= 1) {
            ps += __shfl_down_sync(0xFFFFFFFFu, ps, o);
            pd += __shfl_down_sync(0xFFFFFFFFu, pd, o);
        }
        const int w = c >> 5;
        if ((c & 31) == 0) { red[w][0] = ps; red[w][1] = pd; }
        __syncthreads();
        if (c < 2) {   // c == head index; head h covers warps 2h, 2h+1
            as_[n * 2 + c] = red[2 * c][0] + red[2 * c + 1][0];
            ad_[n * 2 + c] = red[2 * c][1] + red[2 * c + 1][1];
        }
        __syncthreads();
    }
}

// ---------------- kernel S: softmax denominators (1 thread / edge) ------------
__global__ void edge_sum_kernel(const int* __restrict__ ei,
                                const float* __restrict__ as_,
                                const float* __restrict__ ad_,
                                float* __restrict__ s)
{
    const int e = blockIdx.x * blockDim.x + threadIdx.x;
    if (e >= EE + NN) return;
    int src, dst;
    if (e < EE) { src = ei[e]; dst = ei[EE + e]; }
    else        { src = dst = e - EE; }
    const float2 a_s = reinterpret_cast<const float2*>(as_)[src];
    const float2 a_d = reinterpret_cast<const float2*>(ad_)[dst];
    float e0 = a_s.x + a_d.x; e0 = e0 > 0.f ? e0 : 0.2f * e0;
    float e1 = a_s.y + a_d.y; e1 = e1 > 0.f ? e1 : 0.2f * e1;
    atomicAdd(&s[dst * 2 + 0], __expf(e0));
    atomicAdd(&s[dst * 2 + 1], __expf(e1));
}

// ---------------- kernel P: weighted scatter (1 warp / edge) ------------------
__global__ void edge_prop_kernel(const int* __restrict__ ei,
                                 const float* __restrict__ as_,
                                 const float* __restrict__ ad_,
                                 const float* __restrict__ s,
                                 const float* __restrict__ xw,
                                 float* __restrict__ hcat,
                                 int cat_off)
{
    const int gtid = blockIdx.x * blockDim.x + threadIdx.x;
    const int e    = gtid >> 5;
    const int lane = threadIdx.x & 31;
    if (e >= EE + NN) return;
    int src, dst;
    if (e < EE) { src = ei[e]; dst = ei[EE + e]; }
    else        { src = dst = e - EE; }
    const int h = lane >> 4;                    // lanes 0-15 head0, 16-31 head1
    const float a_s = as_[src * 2 + h];
    const float a_d = ad_[dst * 2 + h];
    float ev = a_s + a_d; ev = ev > 0.f ? ev : 0.2f * ev;
    const float alpha = __expf(ev) / s[dst * 2 + h];

    const float4 v = reinterpret_cast<const float4*>(xw + src * HC)[lane];
    float* o = hcat + (long)dst * FUSED + cat_off + lane * 4;
    atomicAdd(o + 0, v.x * alpha);
    atomicAdd(o + 1, v.y * alpha);
    atomicAdd(o + 2, v.z * alpha);
    atomicAdd(o + 3, v.w * alpha);
}

// ---------------- epilogue: bias + ELU over Hcat ------------------------------
__global__ void elu_bias_kernel(float* __restrict__ hcat,
                                const float* __restrict__ b0,
                                const float* __restrict__ b1,
                                const float* __restrict__ b2)
{
    const long total = (long)NN * FUSED;
    for (long i = (long)blockIdx.x * blockDim.x + threadIdx.x; i < total;
         i += (long)gridDim.x * blockDim.x) {
        const int col = (int)(i % FUSED);
        const float* b = col < 128 ? b0 : (col < 256 ? b1 : b2);
        float v = hcat[i] + b[col & 127];
        hcat[i] = v > 0.f ? v : expm1f(v);
    }
}

// ---------------- fused MLP: out = relu(Hcat@Wc1+bc1) @ Wc2 + bc2 -------------
template <int RT>
__global__ void mlp_kernel(const float* __restrict__ hcat,
                           const float* __restrict__ Wc1,
                           const float* __restrict__ bc1,
                           const float* __restrict__ Wc2,
                           const float* __restrict__ bc2,
                           float* __restrict__ out)
{
    __shared__ float hs[RT * FUSED];
    __shared__ float red[4];
    const int j = threadIdx.x;          // 0..127 hidden unit
    const float w2 = Wc2[j];
    const float b1 = bc1[j];
    const float b2 = bc2[0];
    const int ngroups = NN / RT;
    for (int g = blockIdx.x; g < ngroups; g += gridDim.x) {
        const int n0 = g * RT;
        __syncthreads();
        for (int i = j; i < RT * FUSED; i += 128)
            hs[i] = hcat[n0 * FUSED + i];
        __syncthreads();
        float acc[RT];
#pragma unroll
        for (int r = 0; r < RT; r++) acc[r] = b1;
#pragma unroll 4
        for (int k = 0; k < FUSED; k++) {
            const float w = Wc1[k * 128 + j];
#pragma unroll
            for (int r = 0; r < RT; r++) acc[r] += hs[r * FUSED + k] * w;
        }
#pragma unroll
        for (int r = 0; r < RT; r++) {
            float h = acc[r] > 0.f ? acc[r] : 0.f;
            float p = h * w2;
#pragma unroll
            for (int o = 16; o; o >>= 1) p += __shfl_down_sync(0xFFFFFFFFu, p, o);
            if ((j & 31) == 0) red[j >> 5] = p;
            __syncthreads();
            if (j == 0) out[n0 + r] = red[0] + red[1] + red[2] + red[3] + b2;
            __syncthreads();
        }
    }
}

// ---------------- host orchestration ------------------------------------------
extern "C" void kernel_launch(void* const* d_in, const int* in_sizes, int n_in,
                              void* d_out, int out_size)
{
    // inputs per reference signature order:
    // per cat i: x{i}, ei{i}, W{i}, att_s{i}, att_d{i}, bias{i}   (6 each)
    // then Wc1, bc1, Wc2, bc2
    const float* x[3];  const int* ei[3]; const float* W[3];
    const float* atts[3]; const float* attd[3]; const float* bias[3];
    for (int i = 0; i < 3; i++) {
        x[i]    = (const float*)d_in[6 * i + 0];
        ei[i]   = (const int*)  d_in[6 * i + 1];
        W[i]    = (const float*)d_in[6 * i + 2];
        atts[i] = (const float*)d_in[6 * i + 3];
        attd[i] = (const float*)d_in[6 * i + 4];
        bias[i] = (const float*)d_in[6 * i + 5];
    }
    const float* Wc1 = (const float*)d_in[18];
    const float* bc1 = (const float*)d_in[19];
    const float* Wc2 = (const float*)d_in[20];
    const float* bc2 = (const float*)d_in[21];
    float* out = (float*)d_out;

    float *p_xw, *p_as, *p_ad, *p_s, *p_hcat;
    cudaGetSymbolAddress((void**)&p_xw,   g_xw);
    cudaGetSymbolAddress((void**)&p_as,   g_as);
    cudaGetSymbolAddress((void**)&p_ad,   g_ad);
    cudaGetSymbolAddress((void**)&p_s,    g_s);
    cudaGetSymbolAddress((void**)&p_hcat, g_hcat);

    cudaMemsetAsync(p_s, 0, sizeof(float) * 3 * NN * 2);
    cudaMemsetAsync(p_hcat, 0, sizeof(float) * (size_t)NN * FUSED);

    const int GEMM_GRID = 1184;   // 8 blocks/SM
    const int EDGE_T = EE + NN;

    for (int c = 0; c < 3; c++) {
        float* xw  = p_xw + (size_t)c * NN * HC;
        float* as_ = p_as + (size_t)c * NN * 2;
        float* ad_ = p_ad + (size_t)c * NN * 2;
        float* s_  = p_s  + (size_t)c * NN * 2;

        if (c < 2) gemm_xw_kernel<128, 8><<<GEMM_GRID, 128>>>(x[c], W[c], xw);
        else       gemm_xw_kernel< 64, 8><<<GEMM_GRID, 128>>>(x[c], W[c], xw);

        att_dots_kernel<<<2960, 128>>>(xw, atts[c], attd[c], as_, ad_);

        edge_sum_kernel<<<(EDGE_T + 255) / 256, 256>>>(ei[c], as_, ad_, s_);

        edge_prop_kernel<<<(EDGE_T * 32 + 255) / 256, 256>>>(
            ei[c], as_, ad_, s_, xw, p_hcat, c * HC);
    }

    elu_bias_kernel<<<4736, 256>>>(p_hcat, bias[0], bias[1], bias[2]);

    mlp_kernel<8><<<GEMM_GRID, 128>>>(p_hcat, Wc1, bc1, Wc2, bc2, out);
}

// round 2
// speedup vs baseline: 1.6301x; 1.6301x over previous
#include <cuda_runtime.h>
#include <cuda_bf16.h>
#include <math.h>

#define NN 40000
#define EE 600000
#define HC 128          // H*C
#define FUSED 384

// ---------------- scratch (device globals; no allocation allowed) -------------
__device__ __align__(16) float g_xw[3][NN * HC];   // transformed features
__device__ float g_as[3][NN * 2];                  // a_src per node/head
__device__ float g_ad[3][NN * 2];                  // a_dst per node/head
__device__ float g_s [3][NN * 2];                  // softmax denominators
__device__ __align__(16) float g_hcat[NN * FUSED]; // unnormalized accumulators

// vector reduction: one 16B atomic instead of 4 scalar ones
__device__ __forceinline__ void red_add_v4(float* p, float a, float b, float c, float d)
{
    asm volatile("red.global.add.v4.f32 [%0], {%1,%2,%3,%4};"
                 :: "l"(p), "f"(a), "f"(b), "f"(c), "f"(d) : "memory");
}

// ---------------- kernel A: xw = x @ W  + fused attention dots ----------------
template <int DIN, int RT>
__global__ void gemm_xw_kernel(const float* __restrict__ x,
                               const float* __restrict__ W,
                               const float* __restrict__ att_s,
                               const float* __restrict__ att_d,
                               float* __restrict__ xw,
                               float* __restrict__ as_,
                               float* __restrict__ ad_)
{
    __shared__ __align__(16) float xs[RT * DIN];
    __shared__ float redbuf[4][2];
    const int c = threadIdx.x;              // 0..127 output column
    const float vs = att_s[c];
    const float vd = att_d[c];
    const int ngroups = NN / RT;
    for (int g = blockIdx.x; g < ngroups; g += gridDim.x) {
        const int n0 = g * RT;
        __syncthreads();
        for (int i = threadIdx.x; i < RT * DIN; i += 128)
            xs[i] = x[n0 * DIN + i];
        __syncthreads();
        float acc[RT];
#pragma unroll
        for (int r = 0; r < RT; r++) acc[r] = 0.f;
#pragma unroll
        for (int k = 0; k < DIN; k += 4) {
            const float w0 = W[(k + 0) * HC + c];
            const float w1 = W[(k + 1) * HC + c];
            const float w2 = W[(k + 2) * HC + c];
            const float w3 = W[(k + 3) * HC + c];
#pragma unroll
            for (int r = 0; r < RT; r++) {
                const float4 xv = *reinterpret_cast<const float4*>(&xs[r * DIN + k]);
                acc[r] += xv.x * w0 + xv.y * w1 + xv.z * w2 + xv.w * w3;
            }
        }
#pragma unroll
        for (int r = 0; r < RT; r++) xw[(n0 + r) * HC + c] = acc[r];
        // fused attention dots: reduce acc[r]*att over the 128 columns held here
        const int w = c >> 5;
#pragma unroll
        for (int r = 0; r < RT; r++) {
            float ps = acc[r] * vs, pd = acc[r] * vd;
#pragma unroll
            for (int o = 16; o; o >>= 1) {
                ps += __shfl_down_sync(0xFFFFFFFFu, ps, o);
                pd += __shfl_down_sync(0xFFFFFFFFu, pd, o);
            }
            if ((c & 31) == 0) { redbuf[w][0] = ps; redbuf[w][1] = pd; }
            __syncthreads();
            if (c < 2) {   // head h covers warps 2h, 2h+1
                as_[(n0 + r) * 2 + c] = redbuf[2 * c][0] + redbuf[2 * c + 1][0];
                ad_[(n0 + r) * 2 + c] = redbuf[2 * c][1] + redbuf[2 * c + 1][1];
            }
            __syncthreads();
        }
    }
}

// ---------------- kernel P: unnormalized scatter + denominator (1 warp/edge) --
__global__ void edge_prop_kernel(const int* __restrict__ ei,
                                 const float* __restrict__ as_,
                                 const float* __restrict__ ad_,
                                 float* __restrict__ s,
                                 const float* __restrict__ xw,
                                 float* __restrict__ hcat,
                                 int cat_off)
{
    const int e    = (blockIdx.x * blockDim.x + threadIdx.x) >> 5;
    const int lane = threadIdx.x & 31;
    if (e >= EE + NN) return;
    int src, dst;
    if (e < EE) { src = __ldg(ei + e); dst = __ldg(ei + EE + e); }
    else        { src = dst = e - EE; }
    const int h = lane >> 4;                    // lanes 0-15 head0, 16-31 head1
    float ev = as_[src * 2 + h] + ad_[dst * 2 + h];
    ev = ev > 0.f ? ev : 0.2f * ev;
    const float ex = __expf(ev);
    if ((lane & 15) == 0) atomicAdd(&s[dst * 2 + h], ex);
    const float4 v = reinterpret_cast<const float4*>(xw + src * HC)[lane];
    float* o = hcat + (long)dst * FUSED + cat_off + lane * 4;
    red_add_v4(o, v.x * ex, v.y * ex, v.z * ex, v.w * ex);
}

// ---------------- fused MLP: normalize + bias + ELU + 2-layer MLP -------------
template <int RT>
__global__ void mlp_kernel(const float* __restrict__ hcat,
                           const float* __restrict__ s,      // [3][NN*2]
                           const float* __restrict__ b0,
                           const float* __restrict__ b1,
                           const float* __restrict__ b2,
                           const float* __restrict__ Wc1,
                           const float* __restrict__ bc1,
                           const float* __restrict__ Wc2,
                           const float* __restrict__ bc2,
                           float* __restrict__ out)
{
    __shared__ __align__(16) float hs[RT * FUSED];
    __shared__ float red[4];
    const int j  = threadIdx.x;          // 0..127 hidden unit / column-in-cat
    const int hh = j >> 6;               // head for column j
    const float w2  = Wc2[j];
    const float b1c = bc1[j];
    const float b2c = bc2[0];
    const float bv0 = b0[j], bv1 = b1[j], bv2 = b2[j];
    const int ngroups = NN / RT;
    for (int g = blockIdx.x; g < ngroups; g += gridDim.x) {
        const int n0 = g * RT;
        __syncthreads();
#pragma unroll
        for (int r = 0; r < RT; r++) {
            const int node = n0 + r;
            const float s0 = s[0 * NN * 2 + node * 2 + hh];
            const float s1 = s[1 * NN * 2 + node * 2 + hh];
            const float s2 = s[2 * NN * 2 + node * 2 + hh];
            float v0 = __fdividef(hcat[(long)node * FUSED +   0 + j], s0) + bv0;
            float v1 = __fdividef(hcat[(long)node * FUSED + 128 + j], s1) + bv1;
            float v2 = __fdividef(hcat[(long)node * FUSED + 256 + j], s2) + bv2;
            hs[r * FUSED +   0 + j] = v0 > 0.f ? v0 : expm1f(v0);
            hs[r * FUSED + 128 + j] = v1 > 0.f ? v1 : expm1f(v1);
            hs[r * FUSED + 256 + j] = v2 > 0.f ? v2 : expm1f(v2);
        }
        __syncthreads();
        float acc[RT];
#pragma unroll
        for (int r = 0; r < RT; r++) acc[r] = b1c;
#pragma unroll
        for (int k = 0; k < FUSED; k += 4) {
            const float w0 = Wc1[(k + 0) * 128 + j];
            const float w1 = Wc1[(k + 1) * 128 + j];
            const float w2_ = Wc1[(k + 2) * 128 + j];
            const float w3 = Wc1[(k + 3) * 128 + j];
#pragma unroll
            for (int r = 0; r < RT; r++) {
                const float4 hv = *reinterpret_cast<const float4*>(&hs[r * FUSED + k]);
                acc[r] += hv.x * w0 + hv.y * w1 + hv.z * w2_ + hv.w * w3;
            }
        }
#pragma unroll
        for (int r = 0; r < RT; r++) {
            float h = acc[r] > 0.f ? acc[r] : 0.f;
            float p = h * w2;
#pragma unroll
            for (int o = 16; o; o >>= 1) p += __shfl_down_sync(0xFFFFFFFFu, p, o);
            if ((j & 31) == 0) red[j >> 5] = p;
            __syncthreads();
            if (j == 0) out[n0 + r] = red[0] + red[1] + red[2] + red[3] + b2c;
            __syncthreads();
        }
    }
}

// ---------------- host orchestration ------------------------------------------
extern "C" void kernel_launch(void* const* d_in, const int* in_sizes, int n_in,
                              void* d_out, int out_size)
{
    const float* x[3];  const int* ei[3]; const float* W[3];
    const float* atts[3]; const float* attd[3]; const float* bias[3];
    for (int i = 0; i < 3; i++) {
        x[i]    = (const float*)d_in[6 * i + 0];
        ei[i]   = (const int*)  d_in[6 * i + 1];
        W[i]    = (const float*)d_in[6 * i + 2];
        atts[i] = (const float*)d_in[6 * i + 3];
        attd[i] = (const float*)d_in[6 * i + 4];
        bias[i] = (const float*)d_in[6 * i + 5];
    }
    const float* Wc1 = (const float*)d_in[18];
    const float* bc1 = (const float*)d_in[19];
    const float* Wc2 = (const float*)d_in[20];
    const float* bc2 = (const float*)d_in[21];
    float* out = (float*)d_out;

    float *p_xw, *p_as, *p_ad, *p_s, *p_hcat;
    cudaGetSymbolAddress((void**)&p_xw,   g_xw);
    cudaGetSymbolAddress((void**)&p_as,   g_as);
    cudaGetSymbolAddress((void**)&p_ad,   g_ad);
    cudaGetSymbolAddress((void**)&p_s,    g_s);
    cudaGetSymbolAddress((void**)&p_hcat, g_hcat);

    cudaMemsetAsync(p_s, 0, sizeof(float) * 3 * NN * 2);
    cudaMemsetAsync(p_hcat, 0, sizeof(float) * (size_t)NN * FUSED);

    const int GEMM_GRID = 1184;   // 8 blocks/SM
    const int EDGE_T = EE + NN;

    for (int c = 0; c < 3; c++) {
        float* xw  = p_xw + (size_t)c * NN * HC;
        float* as_ = p_as + (size_t)c * NN * 2;
        float* ad_ = p_ad + (size_t)c * NN * 2;
        float* s_  = p_s  + (size_t)c * NN * 2;

        if (c < 2) gemm_xw_kernel<128, 8><<<GEMM_GRID, 128>>>(
                       x[c], W[c], atts[c], attd[c], xw, as_, ad_);
        else       gemm_xw_kernel< 64, 8><<<GEMM_GRID, 128>>>(
                       x[c], W[c], atts[c], attd[c], xw, as_, ad_);

        edge_prop_kernel<<<(EDGE_T * 32 + 255) / 256, 256>>>(
            ei[c], as_, ad_, s_, xw, p_hcat, c * HC);
    }

    mlp_kernel<8><<<GEMM_GRID, 128>>>(p_hcat, p_s, bias[0], bias[1], bias[2],
                                      Wc1, bc1, Wc2, bc2, out);
}